// round 4
// baseline (speedup 1.0000x reference)
#include <cuda_runtime.h>
#include <cstdint>

#define NQ   32
#define KCB  1024
#define CD   8
#define DD   1024
#define TT   4096
#define BB   8

#define NWARPS   8
#define NTHREADS 256
#define KM       8              // columns per warp-pair
#define COLS_PB  32             // 4 pairs x 8 cols
#define NBLOCKS  ((BB * TT) / COLS_PB)  // 1024
#define HALF_D   512
#define HALF_K   512

#define QOUT_ELEMS (BB * DD * TT)       // 33554432
#define IDX_ELEMS  (NQ * BB * TT)       // 1048576
#define FULL_OUT   (QOUT_ELEMS + IDX_ELEMS + BB)

// SMEM float offsets
#define OFF_WINT 0
#define OFF_WOUT (DD*12)
#define OFF_CBN  (DD*12*2)
#define OFF_BOUT (DD*12*2 + KCB*12)     // 36864
#define OFF_BIN  (OFF_BOUT + DD)        // 37888
#define OFF_ZE   (OFF_BIN + 8)          // 37896 (x4B = 16B aligned): 256 u64
#define OFF_ZP   (OFF_ZE + 512)         // 256 u64
#define OFF_ARG  (OFF_ZP + 512)         // 64 float2 (4 pairs x 2 warps x 8)
#define SMEM_FLOATS (OFF_ARG + 128)
#define SMEM_BYTES  (SMEM_FLOATS * 4)

typedef unsigned long long u64t;

// ---- f32x2 packed helpers (FFMA2/FADD2 path: only reachable via PTX) ----
__device__ __forceinline__ u64t pk2(float a, float b) {
    u64t r; asm("mov.b64 %0,{%1,%2};" : "=l"(r) : "f"(a), "f"(b)); return r;
}
__device__ __forceinline__ float2 upk2(u64t v) {
    float2 r; asm("mov.b64 {%0,%1},%2;" : "=f"(r.x), "=f"(r.y) : "l"(v)); return r;
}
__device__ __forceinline__ void fma2(u64t& d, u64t a, u64t b) {
    asm("fma.rn.f32x2 %0,%1,%2,%0;" : "+l"(d) : "l"(a), "l"(b));
}
__device__ __forceinline__ u64t mul2(u64t a, u64t b) {
    u64t r; asm("mul.rn.f32x2 %0,%1,%2;" : "=l"(r) : "l"(a), "l"(b)); return r;
}
__device__ __forceinline__ u64t add2(u64t a, u64t b) {
    u64t r; asm("add.rn.f32x2 %0,%1,%2;" : "=l"(r) : "l"(a), "l"(b)); return r;
}

// Precomputed scratch (device globals: no allocation allowed)
__device__ float g_winT[NQ * DD * CD];   // [nq][d][c]
__device__ float g_cbn [NQ * KCB * CD];  // normalized codebooks [nq][k][c]
__device__ int   g_len [BB];

// ---------------------------------------------------------------------------
__global__ void rvq_precompute(const float* __restrict__ W_in,
                               const float* __restrict__ cb,
                               const long long* __restrict__ len64,
                               float* __restrict__ out, int out_size) {
    int tid = blockIdx.x * blockDim.x + threadIdx.x;   // 0 .. 262143
    int nq  = tid >> 13;
    int rem = tid & 8191;
    int d   = rem >> 3;
    int c   = rem & 7;
    g_winT[tid] = W_in[(nq * CD + c) * DD + d];

    if (tid < NQ * KCB) {
        const float* row = cb + (size_t)tid * CD;
        float v[8];
        float n2 = 0.0f;
#pragma unroll
        for (int i = 0; i < 8; i++) { v[i] = row[i]; n2 = fmaf(v[i], v[i], n2); }
        float s = fmaxf(__fsqrt_rn(n2), 1e-12f);
#pragma unroll
        for (int i = 0; i < 8; i++)
            g_cbn[(size_t)tid * CD + i] = __fdiv_rn(v[i], s);
    }

    if (tid == 0) {
        long long tmp[BB];
        bool ok64 = true;
        for (int i = 0; i < BB; i++) {
            tmp[i] = len64[i];
            if (tmp[i] < 0 || tmp[i] > TT) ok64 = false;
        }
        if (ok64) { for (int i = 0; i < BB; i++) g_len[i] = (int)tmp[i]; }
        else      { const int* l32 = (const int*)len64;
                    for (int i = 0; i < BB; i++) g_len[i] = l32[i]; }
        if (out_size >= FULL_OUT)
            for (int i = 0; i < BB; i++)
                out[QOUT_ELEMS + IDX_ELEMS + i] = (float)g_len[i];
    }
}

// ---------------------------------------------------------------------------
// Fused RVQ: warp-pair owns 8 columns; each warp holds half the d-range and
// scans half the codebook. Residual in registers, packed fp32x2 everywhere.
// ---------------------------------------------------------------------------
__global__ void __launch_bounds__(NTHREADS, 1)
rvq_kernel(const float* __restrict__ z,
           const float* __restrict__ b_in,
           const float* __restrict__ W_out,
           const float* __restrict__ b_out,
           const float* __restrict__ cb,
           float* __restrict__ out, int out_size) {
    extern __shared__ float sm[];
    float*  sWinT  = sm + OFF_WINT;
    float*  sWout  = sm + OFF_WOUT;
    float*  sCbn   = sm + OFF_CBN;
    float*  sBout  = sm + OFF_BOUT;
    float*  sBin   = sm + OFF_BIN;
    u64t*   zeBuf  = (u64t*)(sm + OFF_ZE);
    u64t*   zpBuf  = (u64t*)(sm + OFF_ZP);
    float2* argBuf = (float2*)(sm + OFF_ARG);

    const int lane = threadIdx.x & 31;
    const int warp = threadIdx.x >> 5;
    const int pair = warp >> 1;
    const int wh   = warp & 1;          // which d-half / k-half
    const int b    = blockIdx.x >> 7;
    const int t0   = ((blockIdx.x & 127) * COLS_PB) + pair * KM;

    const int len = g_len[b];
    float maskf[KM], nmf[KM];
#pragma unroll
    for (int j = 0; j < KM; j++) {
        maskf[j] = ((t0 + j) < len) ? 1.0f : 0.0f;
        nmf[j]   = -maskf[j];
    }

    // residual (own d-half): r[col][i], d = wh*512 + lane + 32*i
    float r[KM][16];
    const float* zbase = z + ((size_t)b * DD + wh * HALF_D) * TT + t0;
#pragma unroll
    for (int i = 0; i < 16; i++) {
        size_t off = (size_t)(lane + 32 * i) * TT;
        float4 v0 = *reinterpret_cast<const float4*>(zbase + off);
        float4 v1 = *reinterpret_cast<const float4*>(zbase + off + 4);
        r[0][i] = v0.x * maskf[0]; r[1][i] = v0.y * maskf[1];
        r[2][i] = v0.z * maskf[2]; r[3][i] = v0.w * maskf[3];
        r[4][i] = v1.x * maskf[4]; r[5][i] = v1.y * maskf[5];
        r[6][i] = v1.z * maskf[6]; r[7][i] = v1.w * maskf[7];
    }

    const bool write_idx = (out_size >= QOUT_ELEMS + IDX_ELEMS);
    const float* wrow = sWinT + (wh * HALF_D + lane) * 12;
    const float* crow = sCbn  + (wh * HALF_K + lane) * 12;
    const float* orow = sWout + (wh * HALF_D + lane) * 12;
    const float* brow = sBout + wh * HALF_D + lane;

    for (int nq = 0; nq < NQ; nq++) {
        // ---- stage weights (padded 12-float rows) ----
        {
            const float4* srcA = reinterpret_cast<const float4*>(g_winT + (size_t)nq * DD * CD);
            const float4* srcB = reinterpret_cast<const float4*>(W_out  + (size_t)nq * DD * CD);
            const float4* srcC = reinterpret_cast<const float4*>(g_cbn  + (size_t)nq * KCB * CD);
#pragma unroll
            for (int it = 0; it < 8; it++) {
                int f    = it * NTHREADS + threadIdx.x;
                int half = f >> 10;
                int row  = f & 1023;
                int sidx = row * 2 + half;
                *reinterpret_cast<float4*>(&sWinT[row * 12 + half * 4]) = srcA[sidx];
                *reinterpret_cast<float4*>(&sWout[row * 12 + half * 4]) = srcB[sidx];
                *reinterpret_cast<float4*>(&sCbn [row * 12 + half * 4]) = srcC[sidx];
            }
            reinterpret_cast<float4*>(sBout)[threadIdx.x] =
                reinterpret_cast<const float4*>(b_out + (size_t)nq * DD)[threadIdx.x];
            if (threadIdx.x < 2)
                reinterpret_cast<float4*>(sBin)[threadIdx.x] =
                    reinterpret_cast<const float4*>(b_in + (size_t)nq * CD)[threadIdx.x];
        }
        __syncthreads();

        // ---- in_proj partials over own d-half; zv[v], v = col*4 + chpair ----
        u64t zv[32];
#pragma unroll
        for (int v = 0; v < 32; v++) zv[v] = 0ull;
#pragma unroll
        for (int i = 0; i < 16; i++) {
            ulonglong2 wA = *reinterpret_cast<const ulonglong2*>(wrow + i * 384);
            ulonglong2 wB = *reinterpret_cast<const ulonglong2*>(wrow + i * 384 + 4);
#pragma unroll
            for (int j = 0; j < KM; j++) {
                u64t rd = pk2(r[j][i], r[j][i]);
                fma2(zv[j * 4 + 0], wA.x, rd);
                fma2(zv[j * 4 + 1], wA.y, rd);
                fma2(zv[j * 4 + 2], wB.x, rd);
                fma2(zv[j * 4 + 3], wB.y, rd);
            }
        }

        // ---- fold-reduce: lane l ends holding complete warp-sum of value v=l ----
#pragma unroll
        for (int m = 16; m >= 1; m >>= 1) {
            bool hi = (lane & m) != 0;
#pragma unroll
            for (int i = 0; i < m; i++) {
                u64t snd = hi ? zv[i] : zv[i + m];
                u64t rcv = __shfl_xor_sync(0xffffffffu, snd, m);
                u64t kp  = hi ? zv[i + m] : zv[i];
                zv[i] = add2(kp, rcv);
            }
        }

        // ---- combine with partner warp + bias, then warp-local broadcast ----
        zeBuf[(pair * 2 + wh) * 32 + lane] = zv[0];
        __syncthreads();
        u64t tot = add2(zv[0], zeBuf[(pair * 2 + (wh ^ 1)) * 32 + lane]);
        {
            int p2 = (lane & 3) * 2;
            tot = add2(tot, pk2(sBin[p2], sBin[p2 + 1]));
        }
        zpBuf[(pair * 2 + wh) * 32 + lane] = tot;
        __syncwarp();
        u64t zp[32];
        {
            const ulonglong2* zr =
                reinterpret_cast<const ulonglong2*>(&zpBuf[(pair * 2 + wh) * 32]);
#pragma unroll
            for (int q = 0; q < 16; q++) {
                ulonglong2 t = zr[q];
                zp[2 * q] = t.x; zp[2 * q + 1] = t.y;
            }
        }

        // ---- argmax of dot(ze, cbn_k) over own k-half ----
        float best[KM]; int bk[KM];
#pragma unroll
        for (int j = 0; j < KM; j++) { best[j] = -3.4e38f; bk[j] = 0; }
#pragma unroll
        for (int jj = 0; jj < 16; jj++) {
            ulonglong2 cA = *reinterpret_cast<const ulonglong2*>(crow + jj * 384);
            ulonglong2 cB = *reinterpret_cast<const ulonglong2*>(crow + jj * 384 + 4);
            int k = wh * HALF_K + lane + 32 * jj;
#pragma unroll
            for (int j = 0; j < KM; j++) {
                u64t dpp = mul2(zp[j * 4 + 0], cA.x);
                fma2(dpp, zp[j * 4 + 1], cA.y);
                fma2(dpp, zp[j * 4 + 2], cB.x);
                fma2(dpp, zp[j * 4 + 3], cB.y);
                float2 u = upk2(dpp);
                float dp = u.x + u.y;
                if (dp > best[j]) { best[j] = dp; bk[j] = k; }
            }
        }
        // fold argmax: 3 col-fold levels + 2 butterfly levels
#pragma unroll
        for (int m = 16; m >= 4; m >>= 1) {
            int h = m >> 2;                     // 4, 2, 1
            bool hi = (lane & m) != 0;
#pragma unroll
            for (int i = 0; i < h; i++) {
                float sb = hi ? best[i] : best[i + h];
                int   sk = hi ? bk[i]   : bk[i + h];
                float rb = __shfl_xor_sync(0xffffffffu, sb, m);
                int   rk = __shfl_xor_sync(0xffffffffu, sk, m);
                float kb = hi ? best[i + h] : best[i];
                int   kk = hi ? bk[i + h]   : bk[i];
                bool take = (rb > kb) || (rb == kb && rk < kk);
                best[i] = take ? rb : kb;
                bk[i]   = take ? rk : kk;
            }
        }
#pragma unroll
        for (int m = 2; m >= 1; m >>= 1) {
            float rb = __shfl_xor_sync(0xffffffffu, best[0], m);
            int   rk = __shfl_xor_sync(0xffffffffu, bk[0],   m);
            if (rb > best[0] || (rb == best[0] && rk < bk[0])) {
                best[0] = rb; bk[0] = rk;
            }
        }
        if ((lane & 3) == 0) {
            int col = (lane >> 2) & 7;
            argBuf[(pair * 2 + wh) * 8 + col] =
                make_float2(best[0], __int_as_float(bk[0]));
        }
        __syncthreads();

        // ---- combine k-halves (warp0 k's < warp1 k's: strict > keeps first-max) ----
        int bkf[KM];
        {
            const float4* a0 = reinterpret_cast<const float4*>(&argBuf[pair * 16]);
            const float4* a1 = reinterpret_cast<const float4*>(&argBuf[pair * 16 + 8]);
#pragma unroll
            for (int q = 0; q < 4; q++) {
                float4 e0 = a0[q], e1 = a1[q];
                bkf[2 * q]     = (e1.x > e0.x) ? __float_as_int(e1.y) : __float_as_int(e0.y);
                bkf[2 * q + 1] = (e1.z > e0.z) ? __float_as_int(e1.w) : __float_as_int(e0.w);
            }
        }

        // ---- gather raw codewords, negated & mask-scaled ----
        u64t zqn[KM][4];
#pragma unroll
        for (int j = 0; j < KM; j++) {
            const ulonglong2* pcb = reinterpret_cast<const ulonglong2*>(
                cb + ((size_t)nq * KCB + bkf[j]) * CD);
            ulonglong2 qa = __ldg(pcb);
            ulonglong2 qb = __ldg(pcb + 1);
            u64t nm = pk2(nmf[j], nmf[j]);
            zqn[j][0] = mul2(qa.x, nm);
            zqn[j][1] = mul2(qa.y, nm);
            zqn[j][2] = mul2(qb.x, nm);
            zqn[j][3] = mul2(qb.y, nm);
        }

        if (wh == 0 && lane == 0 && write_idx) {
            float* ip = &out[QOUT_ELEMS + ((size_t)(nq * BB + b)) * TT + t0];
            *reinterpret_cast<float4*>(ip) =
                make_float4((float)bkf[0], (float)bkf[1], (float)bkf[2], (float)bkf[3]);
            *reinterpret_cast<float4*>(ip + 4) =
                make_float4((float)bkf[4], (float)bkf[5], (float)bkf[6], (float)bkf[7]);
        }

        // ---- out_proj + residual update over own d-half ----
#pragma unroll
        for (int i = 0; i < 16; i++) {
            ulonglong2 wA = *reinterpret_cast<const ulonglong2*>(orow + i * 384);
            ulonglong2 wB = *reinterpret_cast<const ulonglong2*>(orow + i * 384 + 4);
            float bo = brow[i * 32];
#pragma unroll
            for (int j = 0; j < KM; j++) {
                u64t acc = mul2(wA.x, zqn[j][0]);
                fma2(acc, wA.y, zqn[j][1]);
                fma2(acc, wB.x, zqn[j][2]);
                fma2(acc, wB.y, zqn[j][3]);
                float2 u = upk2(acc);
                r[j][i] = fmaf(bo, nmf[j], r[j][i] + (u.x + u.y));
            }
        }
        __syncthreads();
    }

    // ---- qout = (z - r_final) * mask ----
    if (out_size >= QOUT_ELEMS) {
        float* qb = out + ((size_t)b * DD + wh * HALF_D) * TT + t0;
#pragma unroll
        for (int i = 0; i < 16; i++) {
            size_t off = (size_t)(lane + 32 * i) * TT;
            float4 v0 = *reinterpret_cast<const float4*>(zbase + off);
            float4 v1 = *reinterpret_cast<const float4*>(zbase + off + 4);
            float4 o0, o1;
            o0.x = (v0.x - r[0][i]) * maskf[0];
            o0.y = (v0.y - r[1][i]) * maskf[1];
            o0.z = (v0.z - r[2][i]) * maskf[2];
            o0.w = (v0.w - r[3][i]) * maskf[3];
            o1.x = (v1.x - r[4][i]) * maskf[4];
            o1.y = (v1.y - r[5][i]) * maskf[5];
            o1.z = (v1.z - r[6][i]) * maskf[6];
            o1.w = (v1.w - r[7][i]) * maskf[7];
            *reinterpret_cast<float4*>(qb + off)     = o0;
            *reinterpret_cast<float4*>(qb + off + 4) = o1;
        }
    }
}

// ---------------------------------------------------------------------------
extern "C" void kernel_launch(void* const* d_in, const int* in_sizes, int n_in,
                              void* d_out, int out_size) {
    const float*     z     = (const float*)d_in[0];
    const long long* len   = (const long long*)d_in[1];
    const float*     W_in  = (const float*)d_in[2];
    const float*     b_in  = (const float*)d_in[3];
    const float*     W_out = (const float*)d_in[4];
    const float*     b_out = (const float*)d_in[5];
    const float*     cbk   = (const float*)d_in[6];
    float* out = (float*)d_out;

    cudaFuncSetAttribute(rvq_kernel,
                         cudaFuncAttributeMaxDynamicSharedMemorySize, SMEM_BYTES);

    rvq_precompute<<<(NQ * DD * CD) / NTHREADS, NTHREADS>>>(W_in, cbk, len, out, out_size);
    rvq_kernel<<<NBLOCKS, NTHREADS, SMEM_BYTES>>>(z, b_in, W_out, b_out, cbk, out, out_size);
}

// round 5
// speedup vs baseline: 1.1569x; 1.1569x over previous
#include <cuda_runtime.h>
#include <cstdint>

#define NQ   32
#define KCB  1024
#define CD   8
#define DD   1024
#define TT   4096
#define BB   8

#define KM       4
#define NWARPS   8
#define NTHREADS 256
#define COLS_PB  (KM * NWARPS)          // 32
#define NBLOCKS  ((BB * TT) / COLS_PB)  // 1024

#define QOUT_ELEMS (BB * DD * TT)
#define IDX_ELEMS  (NQ * BB * TT)
#define FULL_OUT   (QOUT_ELEMS + IDX_ELEMS + BB)

// SMEM float offsets: WinT | Cbn | Wout x2 | Bout x2 | Bin x2
#define OFF_WINT 0
#define OFF_CBN  (DD*12)
#define OFF_WOUT (DD*12*2)              // 2 buffers of DD*12
#define OFF_BOUT (DD*12*4)              // 2 buffers of DD
#define OFF_BIN  (OFF_BOUT + 2*DD)      // 2 buffers of 8
#define SMEM_FLOATS (OFF_BIN + 16)
#define SMEM_BYTES  (SMEM_FLOATS * 4)   // 204,864 B

typedef unsigned long long u64t;

// ---- f32x2 packed helpers ----
__device__ __forceinline__ u64t pk2(float a, float b) {
    u64t r; asm("mov.b64 %0,{%1,%2};" : "=l"(r) : "f"(a), "f"(b)); return r;
}
__device__ __forceinline__ float2 upk2(u64t v) {
    float2 r; asm("mov.b64 {%0,%1},%2;" : "=f"(r.x), "=f"(r.y) : "l"(v)); return r;
}
__device__ __forceinline__ void fma2(u64t& d, u64t a, u64t b) {
    asm("fma.rn.f32x2 %0,%1,%2,%0;" : "+l"(d) : "l"(a), "l"(b));
}
__device__ __forceinline__ u64t mul2(u64t a, u64t b) {
    u64t r; asm("mul.rn.f32x2 %0,%1,%2;" : "=l"(r) : "l"(a), "l"(b)); return r;
}
__device__ __forceinline__ u64t add2(u64t a, u64t b) {
    u64t r; asm("add.rn.f32x2 %0,%1,%2;" : "=l"(r) : "l"(a), "l"(b)); return r;
}

// ---- cp.async helpers ----
__device__ __forceinline__ uint32_t s2u(const void* p) {
    uint32_t a;
    asm("{ .reg .u64 t; cvta.to.shared.u64 t, %1; cvt.u32.u64 %0, t; }"
        : "=r"(a) : "l"(p));
    return a;
}
__device__ __forceinline__ void cpa16(uint32_t dst, const void* src) {
    asm volatile("cp.async.ca.shared.global [%0], [%1], 16;" :: "r"(dst), "l"(src));
}
__device__ __forceinline__ void cpa_commit() {
    asm volatile("cp.async.commit_group;");
}
__device__ __forceinline__ void cpa_wait_all() {
    asm volatile("cp.async.wait_group 0;");
}

// Stage one 1024x8 weight array into 12-float padded SMEM rows (block-wide).
__device__ __forceinline__ void pf_weight(float* dst, const float* src) {
    uint32_t d0 = s2u(dst);
#pragma unroll
    for (int it = 0; it < 8; it++) {
        int f    = it * NTHREADS + (int)threadIdx.x;
        int half = f >> 10;
        int row  = f & 1023;
        cpa16(d0 + (uint32_t)(row * 12 + half * 4) * 4u,
              src + (size_t)(row * 2 + half) * 4);
    }
}
__device__ __forceinline__ void pf_bout(float* dst, const float* src) {
    cpa16(s2u(dst) + threadIdx.x * 16u, src + threadIdx.x * 4);
}
__device__ __forceinline__ void pf_bin(float* dst, const float* src) {
    if (threadIdx.x < 2) cpa16(s2u(dst) + threadIdx.x * 16u, src + threadIdx.x * 4);
}

// Precomputed scratch
__device__ float g_winT[NQ * DD * CD];   // [nq][d][c]
__device__ float g_cbn [NQ * KCB * CD];  // normalized codebooks
__device__ int   g_len [BB];

// ---------------------------------------------------------------------------
__global__ void rvq_precompute(const float* __restrict__ W_in,
                               const float* __restrict__ cb,
                               const long long* __restrict__ len64,
                               float* __restrict__ out, int out_size) {
    int tid = blockIdx.x * blockDim.x + threadIdx.x;
    int nq  = tid >> 13;
    int rem = tid & 8191;
    int d   = rem >> 3;
    int c   = rem & 7;
    g_winT[tid] = W_in[(nq * CD + c) * DD + d];

    if (tid < NQ * KCB) {
        const float* row = cb + (size_t)tid * CD;
        float v[8];
        float n2 = 0.0f;
#pragma unroll
        for (int i = 0; i < 8; i++) { v[i] = row[i]; n2 = fmaf(v[i], v[i], n2); }
        float s = fmaxf(__fsqrt_rn(n2), 1e-12f);
#pragma unroll
        for (int i = 0; i < 8; i++)
            g_cbn[(size_t)tid * CD + i] = __fdiv_rn(v[i], s);
    }

    if (tid == 0) {
        long long tmp[BB];
        bool ok64 = true;
        for (int i = 0; i < BB; i++) {
            tmp[i] = len64[i];
            if (tmp[i] < 0 || tmp[i] > TT) ok64 = false;
        }
        if (ok64) { for (int i = 0; i < BB; i++) g_len[i] = (int)tmp[i]; }
        else      { const int* l32 = (const int*)len64;
                    for (int i = 0; i < BB; i++) g_len[i] = l32[i]; }
        if (out_size >= FULL_OUT)
            for (int i = 0; i < BB; i++)
                out[QOUT_ELEMS + IDX_ELEMS + i] = (float)g_len[i];
    }
}

// ---------------------------------------------------------------------------
__global__ void __launch_bounds__(NTHREADS, 1)
rvq_kernel(const float* __restrict__ z,
           const float* __restrict__ b_in,
           const float* __restrict__ W_out,
           const float* __restrict__ b_out,
           const float* __restrict__ cb,
           float* __restrict__ out, int out_size) {
    extern __shared__ float sm[];
    float* sWinT = sm + OFF_WINT;
    float* sCbn  = sm + OFF_CBN;
    float* sWout = sm + OFF_WOUT;        // [buf][1024*12]
    float* sBout = sm + OFF_BOUT;        // [buf][1024]
    float* sBin  = sm + OFF_BIN;         // [buf][8]

    const int lane = threadIdx.x & 31;
    const int warp = threadIdx.x >> 5;
    const int b    = blockIdx.x >> 7;
    const int t0   = ((blockIdx.x & 127) * COLS_PB) + warp * KM;

    // ---- prologue: prefetch all step-0 buffers ----
    pf_weight(sWinT, g_winT);
    pf_weight(sCbn,  g_cbn);
    pf_weight(sWout, W_out);
    pf_bout(sBout, b_out);
    pf_bin(sBin, b_in);
    cpa_commit();

    const int len = g_len[b];
    float maskf[KM], nmf[KM];
#pragma unroll
    for (int j = 0; j < KM; j++) {
        maskf[j] = ((t0 + j) < len) ? 1.0f : 0.0f;
        nmf[j]   = -maskf[j];
    }

    // residual = z * mask
    float r[KM][32];
    const float* zbase = z + ((size_t)b * DD) * TT + t0;
#pragma unroll
    for (int i = 0; i < 32; i++) {
        int d = lane + 32 * i;
        float4 v = *reinterpret_cast<const float4*>(zbase + (size_t)d * TT);
        r[0][i] = v.x * maskf[0];
        r[1][i] = v.y * maskf[1];
        r[2][i] = v.z * maskf[2];
        r[3][i] = v.w * maskf[3];
    }

    const bool write_idx = (out_size >= QOUT_ELEMS + IDX_ELEMS);

    cpa_wait_all();
    __syncthreads();

    for (int nq = 0; nq < NQ; nq++) {
        const int cur = nq & 1;
        const int nxt = (nq + 1) & 1;
        const int nn  = (nq < NQ - 1) ? nq + 1 : nq;   // clamp (redundant last copy)
        const float* sBoutC = sBout + cur * DD;
        const float* sBinC  = sBin  + cur * 8;
        const float* sWoutC = sWout + cur * DD * 12;

        // ---- in_proj: packed accumulate over d ----
        u64t zeA[KM][4];
#pragma unroll
        for (int j = 0; j < KM; j++)
#pragma unroll
            for (int p = 0; p < 4; p++) zeA[j][p] = 0ull;

#pragma unroll
        for (int i = 0; i < 32; i++) {
            int d = lane + 32 * i;
            ulonglong2 wA = *reinterpret_cast<const ulonglong2*>(&sWinT[d * 12]);
            ulonglong2 wB = *reinterpret_cast<const ulonglong2*>(&sWinT[d * 12 + 4]);
#pragma unroll
            for (int j = 0; j < KM; j++) {
                u64t rd = pk2(r[j][i], r[j][i]);
                fma2(zeA[j][0], wA.x, rd);
                fma2(zeA[j][1], wA.y, rd);
                fma2(zeA[j][2], wB.x, rd);
                fma2(zeA[j][3], wB.y, rd);
            }
        }

        // ---- packed butterfly reduce (bit-identical per channel) ----
#pragma unroll
        for (int off = 16; off > 0; off >>= 1) {
#pragma unroll
            for (int j = 0; j < KM; j++)
#pragma unroll
                for (int p = 0; p < 4; p++)
                    zeA[j][p] = add2(zeA[j][p],
                                     __shfl_xor_sync(0xffffffffu, zeA[j][p], off));
        }

        __syncthreads();                     // all warps done with sWinT
        // prefetch next step's WinT / Wout / biases
        pf_weight(sWinT, g_winT + (size_t)nn * DD * CD);
        pf_weight(sWout + nxt * DD * 12, W_out + (size_t)nn * DD * CD);
        pf_bout(sBout + nxt * DD, b_out + (size_t)nn * DD);
        pf_bin(sBin + nxt * 8, b_in + (size_t)nn * CD);
        cpa_commit();

        // add bias (packed)
        u64t zp[KM][4];
        {
            const ulonglong2* bi = reinterpret_cast<const ulonglong2*>(sBinC);
            ulonglong2 b0 = bi[0], b1 = bi[1];
#pragma unroll
            for (int j = 0; j < KM; j++) {
                zp[j][0] = add2(zeA[j][0], b0.x);
                zp[j][1] = add2(zeA[j][1], b0.y);
                zp[j][2] = add2(zeA[j][2], b1.x);
                zp[j][3] = add2(zeA[j][3], b1.y);
            }
        }

        // ---- argmax over dot(ze, cbn_k) ----
        float best[KM];
        int   bk[KM];
#pragma unroll
        for (int j = 0; j < KM; j++) { best[j] = -3.4e38f; bk[j] = 0; }

#pragma unroll
        for (int jj = 0; jj < 32; jj++) {
            int k = lane + 32 * jj;
            ulonglong2 cA = *reinterpret_cast<const ulonglong2*>(&sCbn[k * 12]);
            ulonglong2 cB = *reinterpret_cast<const ulonglong2*>(&sCbn[k * 12 + 4]);
#pragma unroll
            for (int j = 0; j < KM; j++) {
                u64t dpp = mul2(zp[j][0], cA.x);
                fma2(dpp, zp[j][1], cA.y);
                fma2(dpp, zp[j][2], cB.x);
                fma2(dpp, zp[j][3], cB.y);
                float2 u = upk2(dpp);
                float dp = u.x + u.y;
                if (dp > best[j]) { best[j] = dp; bk[j] = k; }
            }
        }
#pragma unroll
        for (int off = 16; off > 0; off >>= 1) {
#pragma unroll
            for (int j = 0; j < KM; j++) {
                float ob = __shfl_xor_sync(0xffffffffu, best[j], off);
                int   ok = __shfl_xor_sync(0xffffffffu, bk[j],  off);
                if (ob > best[j] || (ob == best[j] && ok < bk[j])) {
                    best[j] = ob; bk[j] = ok;
                }
            }
        }

        __syncthreads();                     // all warps done with sCbn
        pf_weight(sCbn, g_cbn + (size_t)nn * KCB * CD);
        cpa_commit();

        // ---- gather raw codewords, negated & mask-scaled ----
        u64t zqn[KM][4];
#pragma unroll
        for (int j = 0; j < KM; j++) {
            const ulonglong2* p = reinterpret_cast<const ulonglong2*>(
                cb + ((size_t)nq * KCB + bk[j]) * CD);
            ulonglong2 qa = __ldg(p);
            ulonglong2 qb = __ldg(p + 1);
            u64t nm = pk2(nmf[j], nmf[j]);
            zqn[j][0] = mul2(qa.x, nm);
            zqn[j][1] = mul2(qa.y, nm);
            zqn[j][2] = mul2(qb.x, nm);
            zqn[j][3] = mul2(qb.y, nm);
        }

        if (lane == 0 && write_idx) {
            float4 iv = make_float4((float)bk[0], (float)bk[1],
                                    (float)bk[2], (float)bk[3]);
            *reinterpret_cast<float4*>(
                &out[QOUT_ELEMS + ((size_t)(nq * BB + b)) * TT + t0]) = iv;
        }

        // ---- out_proj + residual update ----
#pragma unroll
        for (int i = 0; i < 32; i++) {
            int d = lane + 32 * i;
            ulonglong2 wA = *reinterpret_cast<const ulonglong2*>(&sWoutC[d * 12]);
            ulonglong2 wB = *reinterpret_cast<const ulonglong2*>(&sWoutC[d * 12 + 4]);
            float bo = sBoutC[d];
#pragma unroll
            for (int j = 0; j < KM; j++) {
                u64t acc = mul2(wA.x, zqn[j][0]);
                fma2(acc, wA.y, zqn[j][1]);
                fma2(acc, wB.x, zqn[j][2]);
                fma2(acc, wB.y, zqn[j][3]);
                float2 u = upk2(acc);
                r[j][i] = fmaf(bo, nmf[j], r[j][i] + (u.x + u.y));
            }
        }

        cpa_wait_all();                      // next step's buffers landed
        __syncthreads();
    }

    // ---- qout = (z - r_final) * mask ----
    if (out_size >= QOUT_ELEMS) {
        float* qb = out + ((size_t)b * DD) * TT + t0;
#pragma unroll
        for (int i = 0; i < 32; i++) {
            int d = lane + 32 * i;
            float4 v = *reinterpret_cast<const float4*>(zbase + (size_t)d * TT);
            float4 o;
            o.x = (v.x - r[0][i]) * maskf[0];
            o.y = (v.y - r[1][i]) * maskf[1];
            o.z = (v.z - r[2][i]) * maskf[2];
            o.w = (v.w - r[3][i]) * maskf[3];
            *reinterpret_cast<float4*>(qb + (size_t)d * TT) = o;
        }
    }
}

// ---------------------------------------------------------------------------
extern "C" void kernel_launch(void* const* d_in, const int* in_sizes, int n_in,
                              void* d_out, int out_size) {
    const float*     z     = (const float*)d_in[0];
    const long long* len   = (const long long*)d_in[1];
    const float*     W_in  = (const float*)d_in[2];
    const float*     b_in  = (const float*)d_in[3];
    const float*     W_out = (const float*)d_in[4];
    const float*     b_out = (const float*)d_in[5];
    const float*     cbk   = (const float*)d_in[6];
    float* out = (float*)d_out;

    cudaFuncSetAttribute(rvq_kernel,
                         cudaFuncAttributeMaxDynamicSharedMemorySize, SMEM_BYTES);

    rvq_precompute<<<(NQ * DD * CD) / NTHREADS, NTHREADS>>>(W_in, cbk, len, out, out_size);
    rvq_kernel<<<NBLOCKS, NTHREADS, SMEM_BYTES>>>(z, b_in, W_out, b_out, cbk, out, out_size);
}

// round 6
// speedup vs baseline: 1.1802x; 1.0202x over previous
#include <cuda_runtime.h>
#include <cstdint>

#define NQ   32
#define KCB  1024
#define CD   8
#define DD   1024
#define TT   4096
#define BB   8

#define NWARPS   8
#define NTHREADS 256
#define KM       8              // columns per warp-pair
#define COLS_PB  32             // 4 pairs x 8 cols
#define NBLOCKS  ((BB * TT) / COLS_PB)  // 1024
#define HALF_D   512

#define QOUT_ELEMS (BB * DD * TT)
#define IDX_ELEMS  (NQ * BB * TT)
#define FULL_OUT   (QOUT_ELEMS + IDX_ELEMS + BB)

// SMEM float offsets
#define OFF_WINT 0
#define OFF_WOUT (DD*12)
#define OFF_CBN  (DD*12*2)
#define OFF_BOUT (DD*12*3)              // 36864
#define OFF_BIN  (OFF_BOUT + DD)        // 37888
#define OFF_ZE   (OFF_BIN + 8)          // 37896 (8B aligned): 8 warps x 32 u64
#define OFF_ARG  (OFF_ZE + 512)         // 32 ints (4 pairs x 8 cols)
#define SMEM_FLOATS (OFF_ARG + 32)
#define SMEM_BYTES  (SMEM_FLOATS * 4)   // ~153.7 KB

typedef unsigned long long u64t;

// ---- f32x2 packed helpers (FFMA2/FADD2 path: only reachable via PTX) ----
__device__ __forceinline__ u64t pk2(float a, float b) {
    u64t r; asm("mov.b64 %0,{%1,%2};" : "=l"(r) : "f"(a), "f"(b)); return r;
}
__device__ __forceinline__ float2 upk2(u64t v) {
    float2 r; asm("mov.b64 {%0,%1},%2;" : "=f"(r.x), "=f"(r.y) : "l"(v)); return r;
}
__device__ __forceinline__ void fma2(u64t& d, u64t a, u64t b) {
    asm("fma.rn.f32x2 %0,%1,%2,%0;" : "+l"(d) : "l"(a), "l"(b));
}
__device__ __forceinline__ u64t mul2(u64t a, u64t b) {
    u64t r; asm("mul.rn.f32x2 %0,%1,%2;" : "=l"(r) : "l"(a), "l"(b)); return r;
}
__device__ __forceinline__ u64t add2(u64t a, u64t b) {
    u64t r; asm("add.rn.f32x2 %0,%1,%2;" : "=l"(r) : "l"(a), "l"(b)); return r;
}

// Precomputed scratch (device globals: no allocation allowed)
__device__ float g_winT[NQ * DD * CD];   // [nq][d][c]
__device__ float g_cbn [NQ * KCB * CD];  // normalized codebooks [nq][k][c]
__device__ int   g_len [BB];

// ---------------------------------------------------------------------------
__global__ void rvq_precompute(const float* __restrict__ W_in,
                               const float* __restrict__ cb,
                               const long long* __restrict__ len64,
                               float* __restrict__ out, int out_size) {
    int tid = blockIdx.x * blockDim.x + threadIdx.x;
    int nq  = tid >> 13;
    int rem = tid & 8191;
    int d   = rem >> 3;
    int c   = rem & 7;
    g_winT[tid] = W_in[(nq * CD + c) * DD + d];

    if (tid < NQ * KCB) {
        const float* row = cb + (size_t)tid * CD;
        float v[8];
        float n2 = 0.0f;
#pragma unroll
        for (int i = 0; i < 8; i++) { v[i] = row[i]; n2 = fmaf(v[i], v[i], n2); }
        float s = fmaxf(__fsqrt_rn(n2), 1e-12f);
#pragma unroll
        for (int i = 0; i < 8; i++)
            g_cbn[(size_t)tid * CD + i] = __fdiv_rn(v[i], s);
    }

    if (tid == 0) {
        long long tmp[BB];
        bool ok64 = true;
        for (int i = 0; i < BB; i++) {
            tmp[i] = len64[i];
            if (tmp[i] < 0 || tmp[i] > TT) ok64 = false;
        }
        if (ok64) { for (int i = 0; i < BB; i++) g_len[i] = (int)tmp[i]; }
        else      { const int* l32 = (const int*)len64;
                    for (int i = 0; i < BB; i++) g_len[i] = l32[i]; }
        if (out_size >= FULL_OUT)
            for (int i = 0; i < BB; i++)
                out[QOUT_ELEMS + IDX_ELEMS + i] = (float)g_len[i];
    }
}

// ---------------------------------------------------------------------------
// Fused RVQ: warp pair co-owns 8 columns. Each warp holds half the residual
// d-range (r[8][16], 128 regs). in_proj/out_proj LDS is amortized over 8 cols;
// argmax runs per-warp over the FULL codebook for its own 4 cols (R2-identical
// semantics, small registers).
// ---------------------------------------------------------------------------
__global__ void __launch_bounds__(NTHREADS, 1)
rvq_kernel(const float* __restrict__ z,
           const float* __restrict__ b_in,
           const float* __restrict__ W_out,
           const float* __restrict__ b_out,
           const float* __restrict__ cb,
           float* __restrict__ out, int out_size) {
    extern __shared__ float sm[];
    float* sWinT = sm + OFF_WINT;
    float* sWout = sm + OFF_WOUT;
    float* sCbn  = sm + OFF_CBN;
    float* sBout = sm + OFF_BOUT;
    float* sBin  = sm + OFF_BIN;
    u64t*  zeBuf = (u64t*)(sm + OFF_ZE);      // [warp][32]
    int*   argBuf = (int*)(sm + OFF_ARG);     // [pair][8]

    const int lane = threadIdx.x & 31;
    const int warp = threadIdx.x >> 5;
    const int pair = warp >> 1;
    const int wh   = warp & 1;                // d-half / argmax col-half
    const int b    = blockIdx.x >> 7;
    const int t0   = ((blockIdx.x & 127) * COLS_PB) + pair * KM;

    const int len = g_len[b];
    float maskf[KM], nmf[KM];
#pragma unroll
    for (int j = 0; j < KM; j++) {
        maskf[j] = ((t0 + j) < len) ? 1.0f : 0.0f;
        nmf[j]   = -maskf[j];
    }

    // residual (own d-half): r[col][i], d = wh*512 + lane + 32*i
    float r[KM][16];
    const float* zbase = z + ((size_t)b * DD + wh * HALF_D) * TT + t0;
#pragma unroll
    for (int i = 0; i < 16; i++) {
        size_t off = (size_t)(lane + 32 * i) * TT;
        float4 v0 = *reinterpret_cast<const float4*>(zbase + off);
        float4 v1 = *reinterpret_cast<const float4*>(zbase + off + 4);
        r[0][i] = v0.x * maskf[0]; r[1][i] = v0.y * maskf[1];
        r[2][i] = v0.z * maskf[2]; r[3][i] = v0.w * maskf[3];
        r[4][i] = v1.x * maskf[4]; r[5][i] = v1.y * maskf[5];
        r[6][i] = v1.z * maskf[6]; r[7][i] = v1.w * maskf[7];
    }

    const bool write_idx = (out_size >= QOUT_ELEMS + IDX_ELEMS);
    const float* wrow = sWinT + (wh * HALF_D + lane) * 12;
    const float* orow = sWout + (wh * HALF_D + lane) * 12;
    const float* brow = sBout + wh * HALF_D + lane;

    for (int nq = 0; nq < NQ; nq++) {
        // ---- stage this step's weights into SMEM (padded 12-float rows) ----
        {
            const float4* srcA = reinterpret_cast<const float4*>(g_winT + (size_t)nq * DD * CD);
            const float4* srcB = reinterpret_cast<const float4*>(W_out  + (size_t)nq * DD * CD);
            const float4* srcC = reinterpret_cast<const float4*>(g_cbn  + (size_t)nq * KCB * CD);
#pragma unroll
            for (int it = 0; it < 8; it++) {
                int f    = it * NTHREADS + (int)threadIdx.x;
                int half = f >> 10;
                int row  = f & 1023;
                int sidx = row * 2 + half;
                *reinterpret_cast<float4*>(&sWinT[row * 12 + half * 4]) = srcA[sidx];
                *reinterpret_cast<float4*>(&sWout[row * 12 + half * 4]) = srcB[sidx];
                *reinterpret_cast<float4*>(&sCbn [row * 12 + half * 4]) = srcC[sidx];
            }
            reinterpret_cast<float4*>(sBout)[threadIdx.x] =
                reinterpret_cast<const float4*>(b_out + (size_t)nq * DD)[threadIdx.x];
            if (threadIdx.x < 2)
                reinterpret_cast<float4*>(sBin)[threadIdx.x] =
                    reinterpret_cast<const float4*>(b_in + (size_t)nq * CD)[threadIdx.x];
        }
        __syncthreads();

        // ---- in_proj partials over own d-half: zv[v], v = col*4 + chpair ----
        {
            u64t zv[32];
#pragma unroll
            for (int v = 0; v < 32; v++) zv[v] = 0ull;
#pragma unroll
            for (int i = 0; i < 16; i++) {
                ulonglong2 wA = *reinterpret_cast<const ulonglong2*>(wrow + i * 384);
                ulonglong2 wB = *reinterpret_cast<const ulonglong2*>(wrow + i * 384 + 4);
#pragma unroll
                for (int j = 0; j < KM; j++) {
                    u64t rd = pk2(r[j][i], r[j][i]);
                    fma2(zv[j * 4 + 0], wA.x, rd);
                    fma2(zv[j * 4 + 1], wA.y, rd);
                    fma2(zv[j * 4 + 2], wB.x, rd);
                    fma2(zv[j * 4 + 3], wB.y, rd);
                }
            }

            // fold-reduce: lane l ends holding the warp-sum of value v = l
#pragma unroll
            for (int m = 16; m >= 1; m >>= 1) {
                bool hi = (lane & m) != 0;
#pragma unroll
                for (int i = 0; i < m; i++) {
                    u64t snd = hi ? zv[i] : zv[i + m];
                    u64t rcv = __shfl_xor_sync(0xffffffffu, snd, m);
                    u64t kp  = hi ? zv[i + m] : zv[i];
                    zv[i] = add2(kp, rcv);
                }
            }
            zeBuf[warp * 32 + lane] = zv[0];
        }
        __syncthreads();

        // combine with partner warp's d-half partials + bias; redistribute
        {
            u64t tot = add2(zeBuf[warp * 32 + lane],
                            zeBuf[(warp ^ 1) * 32 + lane]);
            int p2 = (lane & 3) * 2;
            tot = add2(tot, pk2(sBin[p2], sBin[p2 + 1]));
            zeBuf[warp * 32 + lane] = tot;
        }
        __syncwarp();

        // broadcast-load the 16 values for this warp's 4 argmax columns
        u64t zp[16];       // [jl*4 + p], cols cj = wh*4 + jl
        {
            const ulonglong2* zr =
                reinterpret_cast<const ulonglong2*>(&zeBuf[warp * 32 + wh * 16]);
#pragma unroll
            for (int q = 0; q < 8; q++) {
                ulonglong2 t = zr[q];
                zp[2 * q] = t.x; zp[2 * q + 1] = t.y;
            }
        }

        // ---- argmax over dot(ze, cbn_k), full K, own 4 cols ----
        float best[4]; int bk[4];
#pragma unroll
        for (int j = 0; j < 4; j++) { best[j] = -3.4e38f; bk[j] = 0; }
#pragma unroll
        for (int jj = 0; jj < 32; jj++) {
            int k = lane + 32 * jj;
            ulonglong2 cA = *reinterpret_cast<const ulonglong2*>(&sCbn[k * 12]);
            ulonglong2 cB = *reinterpret_cast<const ulonglong2*>(&sCbn[k * 12 + 4]);
#pragma unroll
            for (int j = 0; j < 4; j++) {
                u64t dpp = mul2(zp[j * 4 + 0], cA.x);
                fma2(dpp, zp[j * 4 + 1], cA.y);
                fma2(dpp, zp[j * 4 + 2], cB.x);
                fma2(dpp, zp[j * 4 + 3], cB.y);
                float2 u = upk2(dpp);
                float dp = u.x + u.y;
                if (dp > best[j]) { best[j] = dp; bk[j] = k; }
            }
        }
#pragma unroll
        for (int off = 16; off > 0; off >>= 1) {
#pragma unroll
            for (int j = 0; j < 4; j++) {
                float ob = __shfl_xor_sync(0xffffffffu, best[j], off);
                int   ok = __shfl_xor_sync(0xffffffffu, bk[j],  off);
                if (ob > best[j] || (ob == best[j] && ok < bk[j])) {
                    best[j] = ob; bk[j] = ok;
                }
            }
        }
        if (lane == 0) {
#pragma unroll
            for (int j = 0; j < 4; j++)
                argBuf[pair * 8 + wh * 4 + j] = bk[j];
        }
        __syncthreads();

        // ---- read the pair's 8 winners, gather codewords (negated, masked) ----
        u64t zqn[KM][4];
        int bkf[KM];
#pragma unroll
        for (int j = 0; j < KM; j++) bkf[j] = argBuf[pair * 8 + j];
#pragma unroll
        for (int j = 0; j < KM; j++) {
            const ulonglong2* pcb = reinterpret_cast<const ulonglong2*>(
                cb + ((size_t)nq * KCB + bkf[j]) * CD);
            ulonglong2 qa = __ldg(pcb);
            ulonglong2 qb = __ldg(pcb + 1);
            u64t nm = pk2(nmf[j], nmf[j]);
            zqn[j][0] = mul2(qa.x, nm);
            zqn[j][1] = mul2(qa.y, nm);
            zqn[j][2] = mul2(qb.x, nm);
            zqn[j][3] = mul2(qb.y, nm);
        }

        if (lane == 0 && write_idx) {
            float* ip = &out[QOUT_ELEMS + ((size_t)(nq * BB + b)) * TT + t0 + wh * 4];
            *reinterpret_cast<float4*>(ip) =
                make_float4((float)bkf[wh * 4 + 0], (float)bkf[wh * 4 + 1],
                            (float)bkf[wh * 4 + 2], (float)bkf[wh * 4 + 3]);
        }

        // ---- out_proj + residual update over own d-half ----
#pragma unroll
        for (int i = 0; i < 16; i++) {
            ulonglong2 wA = *reinterpret_cast<const ulonglong2*>(orow + i * 384);
            ulonglong2 wB = *reinterpret_cast<const ulonglong2*>(orow + i * 384 + 4);
            float bo = brow[i * 32];
#pragma unroll
            for (int j = 0; j < KM; j++) {
                u64t acc = mul2(wA.x, zqn[j][0]);
                fma2(acc, wA.y, zqn[j][1]);
                fma2(acc, wB.x, zqn[j][2]);
                fma2(acc, wB.y, zqn[j][3]);
                float2 u = upk2(acc);
                r[j][i] = fmaf(bo, nmf[j], r[j][i] + (u.x + u.y));
            }
        }
        __syncthreads();
    }

    // ---- qout = (z - r_final) * mask ----
    if (out_size >= QOUT_ELEMS) {
        float* qb = out + ((size_t)b * DD + wh * HALF_D) * TT + t0;
#pragma unroll
        for (int i = 0; i < 16; i++) {
            size_t off = (size_t)(lane + 32 * i) * TT;
            float4 v0 = *reinterpret_cast<const float4*>(zbase + off);
            float4 v1 = *reinterpret_cast<const float4*>(zbase + off + 4);
            float4 o0, o1;
            o0.x = (v0.x - r[0][i]) * maskf[0];
            o0.y = (v0.y - r[1][i]) * maskf[1];
            o0.z = (v0.z - r[2][i]) * maskf[2];
            o0.w = (v0.w - r[3][i]) * maskf[3];
            o1.x = (v1.x - r[4][i]) * maskf[4];
            o1.y = (v1.y - r[5][i]) * maskf[5];
            o1.z = (v1.z - r[6][i]) * maskf[6];
            o1.w = (v1.w - r[7][i]) * maskf[7];
            *reinterpret_cast<float4*>(qb + off)     = o0;
            *reinterpret_cast<float4*>(qb + off + 4) = o1;
        }
    }
}

// ---------------------------------------------------------------------------
extern "C" void kernel_launch(void* const* d_in, const int* in_sizes, int n_in,
                              void* d_out, int out_size) {
    const float*     z     = (const float*)d_in[0];
    const long long* len   = (const long long*)d_in[1];
    const float*     W_in  = (const float*)d_in[2];
    const float*     b_in  = (const float*)d_in[3];
    const float*     W_out = (const float*)d_in[4];
    const float*     b_out = (const float*)d_in[5];
    const float*     cbk   = (const float*)d_in[6];
    float* out = (float*)d_out;

    cudaFuncSetAttribute(rvq_kernel,
                         cudaFuncAttributeMaxDynamicSharedMemorySize, SMEM_BYTES);

    rvq_precompute<<<(NQ * DD * CD) / NTHREADS, NTHREADS>>>(W_in, cbk, len, out, out_size);
    rvq_kernel<<<NBLOCKS, NTHREADS, SMEM_BYTES>>>(z, b_in, W_out, b_out, cbk, out, out_size);
}